// round 1
// baseline (speedup 1.0000x reference)
#include <cuda_runtime.h>
#include <math.h>

// Problem dims
#define BB 16
#define LL 512
#define HIDN 768
#define HH 12
#define DD 64
#define NSTRUCT 5
#define BH (BB*HH)   // 192

// ---------------- scratch (device globals: no allocation allowed) ----------------
__device__ float g_Q [BH * LL * DD];                 // [b,h,l,d]
__device__ float g_K [BH * LL * DD];
__device__ float g_V [BH * LL * DD];
__device__ float g_QB[NSTRUCT * BH * LL * DD];       // [s,b,h,l,d]

// =============================================================================
// Kernel 1: fused QKV projection.
//   out[m, n] = sum_k hs[m,k] * W[n,k] + bias[n]
//   m = b*L + l (8192), n = h*D + d (768). Written to [b,h,l,d] layout.
// Tiling: 64x64 block tile, BK=16, 256 threads, 4x4 micro.
// =============================================================================
__global__ void __launch_bounds__(256) qkv_kernel(
    const float* __restrict__ hs,
    const float* __restrict__ Wq, const float* __restrict__ bq,
    const float* __restrict__ Wk, const float* __restrict__ bk,
    const float* __restrict__ Wv, const float* __restrict__ bv)
{
    const int z = blockIdx.z;  // 0=Q 1=K 2=V
    const float* W    = (z == 0) ? Wq : (z == 1) ? Wk : Wv;
    const float* bias = (z == 0) ? bq : (z == 1) ? bk : bv;
    float* dst        = (z == 0) ? g_Q : (z == 1) ? g_K : g_V;

    __shared__ __align__(16) float As[16 * 68];  // [k][m], padded
    __shared__ __align__(16) float Bs[16 * 68];  // [k][n], padded

    const int t = threadIdx.x;
    const int m0 = blockIdx.x * 64;
    const int n0 = blockIdx.y * 64;
    const int mload = t >> 2, kv = t & 3;   // tile-load role
    const int ty = t >> 4, tx = t & 15;     // compute role

    float c[4][4];
#pragma unroll
    for (int i = 0; i < 4; i++)
#pragma unroll
        for (int j = 0; j < 4; j++) c[i][j] = 0.f;

    for (int k0 = 0; k0 < HIDN; k0 += 16) {
        float4 a4 = *(const float4*)(hs + (size_t)(m0 + mload) * HIDN + k0 + kv * 4);
        As[(kv*4+0)*68 + mload] = a4.x;
        As[(kv*4+1)*68 + mload] = a4.y;
        As[(kv*4+2)*68 + mload] = a4.z;
        As[(kv*4+3)*68 + mload] = a4.w;
        float4 b4 = *(const float4*)(W + (size_t)(n0 + mload) * HIDN + k0 + kv * 4);
        Bs[(kv*4+0)*68 + mload] = b4.x;
        Bs[(kv*4+1)*68 + mload] = b4.y;
        Bs[(kv*4+2)*68 + mload] = b4.z;
        Bs[(kv*4+3)*68 + mload] = b4.w;
        __syncthreads();
#pragma unroll
        for (int k = 0; k < 16; k++) {
            float4 av4 = *(const float4*)&As[k*68 + ty*4];
            float4 bv4 = *(const float4*)&Bs[k*68 + tx*4];
            float a[4] = {av4.x, av4.y, av4.z, av4.w};
            float bb[4] = {bv4.x, bv4.y, bv4.z, bv4.w};
#pragma unroll
            for (int i = 0; i < 4; i++)
#pragma unroll
                for (int j = 0; j < 4; j++) c[i][j] += a[i] * bb[j];
        }
        __syncthreads();
    }

#pragma unroll
    for (int i = 0; i < 4; i++) {
        int m = m0 + ty*4 + i;
        int b = m >> 9, l = m & 511;
#pragma unroll
        for (int j = 0; j < 4; j++) {
            int n = n0 + tx*4 + j;
            int h = n >> 6, d = n & 63;
            dst[((size_t)(b*HH + h) * LL + l) * DD + d] = c[i][j] + bias[n];
        }
    }
}

// =============================================================================
// Kernel 2: QB[s,b,h,l,:] = Q[b,h,l,:] @ bili[s,h]   (K=64 GEMM)
// grid (128 m-tiles of 64 rows, H, S), 256 threads, 4x4 micro.
// =============================================================================
__global__ void __launch_bounds__(256) qb_kernel(const float* __restrict__ bili)
{
    const int mt = blockIdx.x, h = blockIdx.y, s = blockIdx.z;
    const int m0 = mt * 64;
    const int b = m0 >> 9, l0 = m0 & 511;
    const float* qbase = g_Q + (size_t)(b*HH + h) * LL * DD;
    const float* Bm    = bili + (size_t)(s*HH + h) * DD * DD;   // [k][n]
    float* dst         = g_QB + (size_t)((s*BB + b)*HH + h) * LL * DD;

    __shared__ __align__(16) float As[16 * 68];  // [k][m]
    __shared__ __align__(16) float Bs[16 * 68];  // [k][n]

    const int t = threadIdx.x;
    const int mload = t >> 2, kv = t & 3;
    const int kl = t >> 4, nv = t & 15;
    const int ty = t >> 4, tx = t & 15;

    float c[4][4];
#pragma unroll
    for (int i = 0; i < 4; i++)
#pragma unroll
        for (int j = 0; j < 4; j++) c[i][j] = 0.f;

    for (int k0 = 0; k0 < DD; k0 += 16) {
        float4 a4 = *(const float4*)(qbase + (size_t)(l0 + mload) * DD + k0 + kv * 4);
        As[(kv*4+0)*68 + mload] = a4.x;
        As[(kv*4+1)*68 + mload] = a4.y;
        As[(kv*4+2)*68 + mload] = a4.z;
        As[(kv*4+3)*68 + mload] = a4.w;
        float4 b4 = *(const float4*)(Bm + (size_t)(k0 + kl) * DD + nv * 4);
        Bs[kl*68 + nv*4+0] = b4.x;
        Bs[kl*68 + nv*4+1] = b4.y;
        Bs[kl*68 + nv*4+2] = b4.z;
        Bs[kl*68 + nv*4+3] = b4.w;
        __syncthreads();
#pragma unroll
        for (int k = 0; k < 16; k++) {
            float4 av4 = *(const float4*)&As[k*68 + ty*4];
            float4 bv4 = *(const float4*)&Bs[k*68 + tx*4];
            float a[4] = {av4.x, av4.y, av4.z, av4.w};
            float bb[4] = {bv4.x, bv4.y, bv4.z, bv4.w};
#pragma unroll
            for (int i = 0; i < 4; i++)
#pragma unroll
                for (int j = 0; j < 4; j++) c[i][j] += a[i] * bb[j];
        }
        __syncthreads();
    }

#pragma unroll
    for (int i = 0; i < 4; i++)
#pragma unroll
        for (int j = 0; j < 4; j++)
            dst[(size_t)(l0 + ty*4 + i) * DD + tx*4 + j] = c[i][j];
}

// =============================================================================
// Kernel 3: fused attention.
// Block = (b,h, 32-row q-tile). 256 threads.
//  smem: qall[6][32][64] | ktv (k-tile transposed [64][130] / v-tile [128][66]) | sc[32][512]
//  Phase A: 6 score-component GEMM passes per 128-wide j-tile, masked combine.
//  Phase B: warp-per-row softmax.  Phase C: PV from smem.
// =============================================================================
#define SMEM_FLOATS (6*32*64 + 8448 + 32*512)

__global__ void __launch_bounds__(256) attn_kernel(
    const float* __restrict__ smask,   // [S,B,1,L,L]
    const float* __restrict__ amask,   // [B,1,1,L]
    const float* __restrict__ absb,    // [S,H]
    float* __restrict__ out)           // [B,L,H*D]
{
    extern __shared__ float sh[];
    float* qall = sh;                  // 6*32*64 = 12288
    float* ktv  = sh + 6*32*64;        // 8448
    float* sc   = ktv + 8448;          // 32*512 = 16384

    const int t  = threadIdx.x;
    const int it = blockIdx.x;               // 0..15
    const int bh = blockIdx.y;               // 0..191
    const int b = bh / HH, h = bh % HH;
    const int i0 = it * 32;

    const float* Qb = g_Q + (size_t)bh * LL * DD;
    const float* Kb = g_K + (size_t)bh * LL * DD;
    const float* Vb = g_V + (size_t)bh * LL * DD;

    // ---- load q + 5 qb row-blocks ----
    for (int f = t; f < 6 * 512; f += 256) {
        int c = f >> 9, r = f & 511;
        int i = r >> 4, dv = r & 15;
        const float* src = (c == 0)
            ? (Qb + (size_t)(i0 + i) * DD + dv * 4)
            : (g_QB + (size_t)((c - 1) * BB + b) * HH * LL * DD
                    + (size_t)h * LL * DD + (size_t)(i0 + i) * DD + dv * 4);
        float4 v4 = *(const float4*)src;
        float* dp = qall + (c * 32 + i) * 64 + dv * 4;
        dp[0] = v4.x; dp[1] = v4.y; dp[2] = v4.z; dp[3] = v4.w;
    }
    __syncthreads();

    const int ty = t >> 5, tx = t & 31;      // scores: i = ty*4+ii, j = tx + 32*jj

    // ---- Phase A: scores ----
    for (int jt = 0; jt < 4; ++jt) {
        const int j0 = jt * 128;
        // load K tile transposed: ktv[d*130 + j]
        for (int f = t; f < 2048; f += 256) {
            int j = f >> 4, dv = f & 15;
            float4 v4 = *(const float4*)(Kb + (size_t)(j0 + j) * DD + dv * 4);
            ktv[(dv*4+0)*130 + j] = v4.x;
            ktv[(dv*4+1)*130 + j] = v4.y;
            ktv[(dv*4+2)*130 + j] = v4.z;
            ktv[(dv*4+3)*130 + j] = v4.w;
        }
        __syncthreads();

        for (int c = 0; c < 6; ++c) {
            float acc[4][4];
#pragma unroll
            for (int i = 0; i < 4; i++)
#pragma unroll
                for (int j = 0; j < 4; j++) acc[i][j] = 0.f;

            const float* qr = qall + (c * 32 + ty * 4) * 64;
#pragma unroll
            for (int d4 = 0; d4 < 16; ++d4) {
                float av[4][4];
#pragma unroll
                for (int ii = 0; ii < 4; ++ii) {
                    float4 q4 = *(const float4*)(qr + ii * 64 + d4 * 4);
                    av[ii][0] = q4.x; av[ii][1] = q4.y; av[ii][2] = q4.z; av[ii][3] = q4.w;
                }
#pragma unroll
                for (int e = 0; e < 4; ++e) {
                    const float* kr = &ktv[(d4*4+e)*130 + tx];
                    float kv0 = kr[0], kv1 = kr[32], kv2 = kr[64], kv3 = kr[96];
#pragma unroll
                    for (int ii = 0; ii < 4; ++ii) {
                        acc[ii][0] += av[ii][e] * kv0;
                        acc[ii][1] += av[ii][e] * kv1;
                        acc[ii][2] += av[ii][e] * kv2;
                        acc[ii][3] += av[ii][e] * kv3;
                    }
                }
            }

            if (c == 0) {
#pragma unroll
                for (int ii = 0; ii < 4; ++ii)
#pragma unroll
                    for (int jj = 0; jj < 4; ++jj)
                        sc[(ty*4+ii)*512 + j0 + tx + 32*jj] = acc[ii][jj];
            } else {
                const float ab = absb[(c - 1) * HH + h];
                const float* mbase = smask + (size_t)((c - 1) * BB + b) * LL * LL;
#pragma unroll
                for (int ii = 0; ii < 4; ++ii) {
                    const int ig = i0 + ty*4 + ii;
                    const float* mr = mbase + (size_t)ig * LL;
#pragma unroll
                    for (int jj = 0; jj < 4; ++jj) {
                        const int jg = j0 + tx + 32*jj;
                        float m = mr[jg];
                        sc[(ty*4+ii)*512 + jg] += m * (acc[ii][jj] + ab);
                    }
                }
            }
        }
        __syncthreads();
    }

    // ---- Phase B: softmax (warp per 4 rows) ----
    {
        const int wid = t >> 5, lane = t & 31;
        const float* am = amask + (size_t)b * LL;
        for (int r = wid * 4; r < wid * 4 + 4; ++r) {
            float vals[16];
            float mx = -1e30f;
#pragma unroll
            for (int q = 0; q < 16; ++q) {
                float v = sc[r*512 + lane + 32*q] * 0.125f + am[lane + 32*q];
                vals[q] = v;
                mx = fmaxf(mx, v);
            }
#pragma unroll
            for (int off = 16; off > 0; off >>= 1)
                mx = fmaxf(mx, __shfl_xor_sync(0xffffffffu, mx, off));
            float sum = 0.f;
#pragma unroll
            for (int q = 0; q < 16; ++q) {
                float e = __expf(vals[q] - mx);
                vals[q] = e;
                sum += e;
            }
#pragma unroll
            for (int off = 16; off > 0; off >>= 1)
                sum += __shfl_xor_sync(0xffffffffu, sum, off);
            float inv = 1.f / sum;
#pragma unroll
            for (int q = 0; q < 16; ++q)
                sc[r*512 + lane + 32*q] = vals[q] * inv;
        }
    }
    __syncthreads();

    // ---- Phase C: PV ----
    {
        const int tyv = t >> 4, txv = t & 15;   // i = tyv*2+ii, d = txv + 16*dd
        float ctx[2][4];
#pragma unroll
        for (int i = 0; i < 2; i++)
#pragma unroll
            for (int j = 0; j < 4; j++) ctx[i][j] = 0.f;

        for (int jt = 0; jt < 4; ++jt) {
            const int j0 = jt * 128;
            // load V tile natural: ktv[j*66 + d]
            for (int f = t; f < 2048; f += 256) {
                int j = f >> 4, dv = f & 15;
                float4 v4 = *(const float4*)(Vb + (size_t)(j0 + j) * DD + dv * 4);
                ktv[j*66 + dv*4+0] = v4.x;
                ktv[j*66 + dv*4+1] = v4.y;
                ktv[j*66 + dv*4+2] = v4.z;
                ktv[j*66 + dv*4+3] = v4.w;
            }
            __syncthreads();
#pragma unroll 4
            for (int j = 0; j < 128; ++j) {
                float p0 = sc[(tyv*2+0)*512 + j0 + j];
                float p1 = sc[(tyv*2+1)*512 + j0 + j];
                const float* vr = &ktv[j*66 + txv];
                float v0 = vr[0], v1 = vr[16], v2 = vr[32], v3 = vr[48];
                ctx[0][0] += p0*v0; ctx[0][1] += p0*v1; ctx[0][2] += p0*v2; ctx[0][3] += p0*v3;
                ctx[1][0] += p1*v0; ctx[1][1] += p1*v1; ctx[1][2] += p1*v2; ctx[1][3] += p1*v3;
            }
            __syncthreads();
        }
#pragma unroll
        for (int ii = 0; ii < 2; ++ii) {
            const int ig = i0 + tyv*2 + ii;
#pragma unroll
            for (int dd = 0; dd < 4; ++dd) {
                const int d = txv + 16*dd;
                out[(size_t)(b * LL + ig) * (HH*DD) + h*DD + d] = ctx[ii][dd];
            }
        }
    }
}

// =============================================================================
extern "C" void kernel_launch(void* const* d_in, const int* in_sizes, int n_in,
                              void* d_out, int out_size)
{
    const float* hs   = (const float*)d_in[0];
    const float* am   = (const float*)d_in[1];
    const float* smk  = (const float*)d_in[2];
    const float* Wq   = (const float*)d_in[3];
    const float* bq   = (const float*)d_in[4];
    const float* Wk   = (const float*)d_in[5];
    const float* bk   = (const float*)d_in[6];
    const float* Wv   = (const float*)d_in[7];
    const float* bv   = (const float*)d_in[8];
    const float* bili = (const float*)d_in[9];
    const float* absb = (const float*)d_in[10];
    float* out = (float*)d_out;

    qkv_kernel<<<dim3(128, 12, 3), 256>>>(hs, Wq, bq, Wk, bk, Wv, bv);
    qb_kernel<<<dim3(128, 12, 5), 256>>>(bili);

    const int smem_bytes = SMEM_FLOATS * (int)sizeof(float);
    cudaFuncSetAttribute(attn_kernel, cudaFuncAttributeMaxDynamicSharedMemorySize, smem_bytes);
    attn_kernel<<<dim3(16, 192), 256, smem_bytes>>>(smk, am, absb, out);
}

// round 2
// speedup vs baseline: 1.4254x; 1.4254x over previous
#include <cuda_runtime.h>
#include <math.h>

#define BB 16
#define LL 512
#define HIDN 768
#define HH 12
#define DD 64
#define NSTRUCT 5
#define BH (BB*HH)   // 192

// ---------------- scratch ----------------
__device__ float g_Q [BH * LL * DD];
__device__ float g_K [BH * LL * DD];
__device__ float g_V [BH * LL * DD];
__device__ float g_QB[NSTRUCT * BH * LL * DD];

// =============================================================================
// Kernel 1: fused QKV projection. 128x64 tile, BK=16, 256 thr, 8x4 micro,
// register prefetch across the barrier.
// =============================================================================
__global__ void __launch_bounds__(256) qkv_kernel(
    const float* __restrict__ hs,
    const float* __restrict__ Wq, const float* __restrict__ bq,
    const float* __restrict__ Wk, const float* __restrict__ bk,
    const float* __restrict__ Wv, const float* __restrict__ bv)
{
    const int z = blockIdx.z;
    const float* W    = (z == 0) ? Wq : (z == 1) ? Wk : Wv;
    const float* bias = (z == 0) ? bq : (z == 1) ? bk : bv;
    float* dst        = (z == 0) ? g_Q : (z == 1) ? g_K : g_V;

    __shared__ __align__(16) float As[16 * 132];  // [k][m]
    __shared__ __align__(16) float Bs[16 * 68];   // [k][n]

    const int t  = threadIdx.x;
    const int m0 = blockIdx.x * 128;
    const int n0 = blockIdx.y * 64;
    const int r  = t >> 2;        // 0..63
    const int kq = t & 3;         // k quad
    const int ty = t >> 4;        // 0..15 -> 8 rows each
    const int tx = t & 15;        // 0..15 -> 4 cols each

    float c[8][4];
#pragma unroll
    for (int i = 0; i < 8; i++)
#pragma unroll
        for (int j = 0; j < 4; j++) c[i][j] = 0.f;

    // initial prefetch
    float4 pa0 = *(const float4*)(hs + (size_t)(m0 + r)      * HIDN + kq * 4);
    float4 pa1 = *(const float4*)(hs + (size_t)(m0 + 64 + r) * HIDN + kq * 4);
    float4 pb  = *(const float4*)(W  + (size_t)(n0 + r)      * HIDN + kq * 4);

    for (int k0 = 0; k0 < HIDN; k0 += 16) {
        As[(kq*4+0)*132 + r]      = pa0.x;
        As[(kq*4+1)*132 + r]      = pa0.y;
        As[(kq*4+2)*132 + r]      = pa0.z;
        As[(kq*4+3)*132 + r]      = pa0.w;
        As[(kq*4+0)*132 + 64 + r] = pa1.x;
        As[(kq*4+1)*132 + 64 + r] = pa1.y;
        As[(kq*4+2)*132 + 64 + r] = pa1.z;
        As[(kq*4+3)*132 + 64 + r] = pa1.w;
        Bs[(kq*4+0)*68 + r] = pb.x;
        Bs[(kq*4+1)*68 + r] = pb.y;
        Bs[(kq*4+2)*68 + r] = pb.z;
        Bs[(kq*4+3)*68 + r] = pb.w;
        __syncthreads();

        if (k0 + 16 < HIDN) {
            pa0 = *(const float4*)(hs + (size_t)(m0 + r)      * HIDN + k0 + 16 + kq * 4);
            pa1 = *(const float4*)(hs + (size_t)(m0 + 64 + r) * HIDN + k0 + 16 + kq * 4);
            pb  = *(const float4*)(W  + (size_t)(n0 + r)      * HIDN + k0 + 16 + kq * 4);
        }

#pragma unroll
        for (int k = 0; k < 16; k++) {
            float4 b4 = *(const float4*)&Bs[k*68 + tx*4];
            float4 a0 = *(const float4*)&As[k*132 + ty*8];
            float4 a1 = *(const float4*)&As[k*132 + ty*8 + 4];
            float a[8] = {a0.x,a0.y,a0.z,a0.w,a1.x,a1.y,a1.z,a1.w};
            float bb[4] = {b4.x,b4.y,b4.z,b4.w};
#pragma unroll
            for (int i = 0; i < 8; i++)
#pragma unroll
                for (int j = 0; j < 4; j++) c[i][j] += a[i] * bb[j];
        }
        __syncthreads();
    }

    const int h = n0 >> 6;
    float4 bv4;
    bv4.x = bias[n0 + tx*4 + 0];
    bv4.y = bias[n0 + tx*4 + 1];
    bv4.z = bias[n0 + tx*4 + 2];
    bv4.w = bias[n0 + tx*4 + 3];
#pragma unroll
    for (int i = 0; i < 8; i++) {
        int m = m0 + ty*8 + i;
        int b = m >> 9, l = m & 511;
        float4 o;
        o.x = c[i][0] + bv4.x;
        o.y = c[i][1] + bv4.y;
        o.z = c[i][2] + bv4.z;
        o.w = c[i][3] + bv4.w;
        *(float4*)(dst + ((size_t)(b*HH + h) * LL + l) * DD + tx*4) = o;
    }
}

// =============================================================================
// Kernel 2: QB[s,b,h,l,:] = Q[b,h,l,:] @ bili[s,h]
// =============================================================================
__global__ void __launch_bounds__(256) qb_kernel(const float* __restrict__ bili)
{
    const int mt = blockIdx.x, h = blockIdx.y, s = blockIdx.z;
    const int m0 = mt * 64;
    const int b = m0 >> 9, l0 = m0 & 511;
    const float* qbase = g_Q + (size_t)(b*HH + h) * LL * DD;
    const float* Bm    = bili + (size_t)(s*HH + h) * DD * DD;
    float* dst         = g_QB + (size_t)((s*BB + b)*HH + h) * LL * DD;

    __shared__ __align__(16) float As[16 * 68];
    __shared__ __align__(16) float Bs[16 * 68];

    const int t = threadIdx.x;
    const int mload = t >> 2, kv = t & 3;
    const int kl = t >> 4, nv = t & 15;
    const int ty = t >> 4, tx = t & 15;

    float c[4][4];
#pragma unroll
    for (int i = 0; i < 4; i++)
#pragma unroll
        for (int j = 0; j < 4; j++) c[i][j] = 0.f;

    for (int k0 = 0; k0 < DD; k0 += 16) {
        float4 a4 = *(const float4*)(qbase + (size_t)(l0 + mload) * DD + k0 + kv * 4);
        As[(kv*4+0)*68 + mload] = a4.x;
        As[(kv*4+1)*68 + mload] = a4.y;
        As[(kv*4+2)*68 + mload] = a4.z;
        As[(kv*4+3)*68 + mload] = a4.w;
        float4 b4 = *(const float4*)(Bm + (size_t)(k0 + kl) * DD + nv * 4);
        Bs[kl*68 + nv*4+0] = b4.x;
        Bs[kl*68 + nv*4+1] = b4.y;
        Bs[kl*68 + nv*4+2] = b4.z;
        Bs[kl*68 + nv*4+3] = b4.w;
        __syncthreads();
#pragma unroll
        for (int k = 0; k < 16; k++) {
            float4 av4 = *(const float4*)&As[k*68 + ty*4];
            float4 bv4 = *(const float4*)&Bs[k*68 + tx*4];
            float a[4] = {av4.x, av4.y, av4.z, av4.w};
            float bb[4] = {bv4.x, bv4.y, bv4.z, bv4.w};
#pragma unroll
            for (int i = 0; i < 4; i++)
#pragma unroll
                for (int j = 0; j < 4; j++) c[i][j] += a[i] * bb[j];
        }
        __syncthreads();
    }

#pragma unroll
    for (int i = 0; i < 4; i++)
#pragma unroll
        for (int j = 0; j < 4; j++)
            dst[(size_t)(l0 + ty*4 + i) * DD + tx*4 + j] = c[i][j];
}

// =============================================================================
// Kernel 3: fused attention, flash-style online softmax.
// Block = (b,h, 64-row q-tile). 256 threads = 8 warps; warp w owns rows w*8..+8.
// Lane covers cols tx+32*jj (jj=0..3) within a 128-wide j-tile.
// smem: qall[6][64][64] | kt[64][130] | vt[128][66] | probs[64][132]
// =============================================================================
#define ATTN_SMEM_FLOATS (6*64*64 + 64*130 + 128*66 + 64*132)

__device__ __forceinline__ float warp_max(float v) {
#pragma unroll
    for (int off = 16; off > 0; off >>= 1)
        v = fmaxf(v, __shfl_xor_sync(0xffffffffu, v, off));
    return v;
}
__device__ __forceinline__ float warp_sum(float v) {
#pragma unroll
    for (int off = 16; off > 0; off >>= 1)
        v += __shfl_xor_sync(0xffffffffu, v, off);
    return v;
}

__global__ void __launch_bounds__(256) attn_kernel(
    const float* __restrict__ smask,   // [S,B,1,L,L]
    const float* __restrict__ amask,   // [B,1,1,L]
    const float* __restrict__ absb,    // [S,H]
    float* __restrict__ out)           // [B,L,H*D]
{
    extern __shared__ float sh[];
    float* qall  = sh;                        // 24576
    float* kt    = sh + 6*64*64;              // 8320  [d][j] pad 130
    float* vt    = kt + 64*130;               // 8448  [j][d] pad 66
    float* probs = vt + 128*66;               // 8448  [row][j] pad 132

    const int t    = threadIdx.x;
    const int w    = t >> 5;
    const int lane = t & 31;
    const int bh   = blockIdx.y;
    const int b = bh / HH, h = bh % HH;
    const int i0 = blockIdx.x * 64;

    const float* Qb = g_Q + (size_t)bh * LL * DD;
    const float* Kb = g_K + (size_t)bh * LL * DD;
    const float* Vb = g_V + (size_t)bh * LL * DD;

    // ---- load q + 5 qb row-blocks into qall ----
    for (int f = t; f < 6 * 64 * 16; f += 256) {
        int c = f >> 10;            // component
        int r = (f >> 4) & 63;      // local row
        int dv = f & 15;            // float4 index
        const float* src = (c == 0)
            ? (Qb + (size_t)(i0 + r) * DD + dv * 4)
            : (g_QB + (size_t)((c - 1) * BB + b) * HH * LL * DD
                    + (size_t)h * LL * DD + (size_t)(i0 + r) * DD + dv * 4);
        float4 v4 = *(const float4*)src;
        float* dp = qall + (c * 64 + r) * 64 + dv * 4;
        dp[0] = v4.x; dp[1] = v4.y; dp[2] = v4.z; dp[3] = v4.w;
    }

    float ab[NSTRUCT];
#pragma unroll
    for (int s = 0; s < NSTRUCT; ++s) ab[s] = __ldg(absb + s*HH + h);

    float mrow[8], lrow[8], ctx[8][2];
#pragma unroll
    for (int i = 0; i < 8; ++i) {
        mrow[i] = -1e30f; lrow[i] = 0.f;
        ctx[i][0] = 0.f; ctx[i][1] = 0.f;
    }

    const int row0 = w * 8;

    for (int jt = 0; jt < 4; ++jt) {
        const int j0 = jt * 128;
        __syncthreads();   // protect kt/vt from previous iteration readers
        // load K tile transposed, V tile natural
        for (int f = t; f < 2048; f += 256) {
            int j = f >> 4, dv = f & 15;
            float4 k4 = *(const float4*)(Kb + (size_t)(j0 + j) * DD + dv * 4);
            kt[(dv*4+0)*130 + j] = k4.x;
            kt[(dv*4+1)*130 + j] = k4.y;
            kt[(dv*4+2)*130 + j] = k4.z;
            kt[(dv*4+3)*130 + j] = k4.w;
            float4 v4 = *(const float4*)(Vb + (size_t)(j0 + j) * DD + dv * 4);
            vt[j*66 + dv*4+0] = v4.x;
            vt[j*66 + dv*4+1] = v4.y;
            vt[j*66 + dv*4+2] = v4.z;
            vt[j*66 + dv*4+3] = v4.w;
        }
        __syncthreads();

        float sreg[8][4];
        // ---- component 0: plain q.k ----
#pragma unroll
        for (int i = 0; i < 8; ++i)
#pragma unroll
            for (int j = 0; j < 4; ++j) sreg[i][j] = 0.f;
#pragma unroll 4
        for (int d4 = 0; d4 < 16; ++d4) {
            float kv[4][4];
#pragma unroll
            for (int e = 0; e < 4; ++e) {
                const float* kr = &kt[(d4*4+e)*130 + lane];
                kv[e][0] = kr[0]; kv[e][1] = kr[32]; kv[e][2] = kr[64]; kv[e][3] = kr[96];
            }
            const float* qr = qall + row0 * 64 + d4 * 4;
#pragma unroll
            for (int ii = 0; ii < 8; ++ii) {
                float4 q4 = *(const float4*)(qr + ii * 64);
                float qe[4] = {q4.x, q4.y, q4.z, q4.w};
#pragma unroll
                for (int e = 0; e < 4; ++e)
#pragma unroll
                    for (int jj = 0; jj < 4; ++jj)
                        sreg[ii][jj] += qe[e] * kv[e][jj];
            }
        }

        // ---- components 1..5: masked bilinear ----
        for (int s = 0; s < NSTRUCT; ++s) {
            float acc[8][4];
#pragma unroll
            for (int i = 0; i < 8; ++i)
#pragma unroll
                for (int j = 0; j < 4; ++j) acc[i][j] = 0.f;
            const float* qc = qall + ((s + 1) * 64 + row0) * 64;
#pragma unroll 4
            for (int d4 = 0; d4 < 16; ++d4) {
                float kv[4][4];
#pragma unroll
                for (int e = 0; e < 4; ++e) {
                    const float* kr = &kt[(d4*4+e)*130 + lane];
                    kv[e][0] = kr[0]; kv[e][1] = kr[32]; kv[e][2] = kr[64]; kv[e][3] = kr[96];
                }
#pragma unroll
                for (int ii = 0; ii < 8; ++ii) {
                    float4 q4 = *(const float4*)(qc + ii * 64 + d4 * 4);
                    float qe[4] = {q4.x, q4.y, q4.z, q4.w};
#pragma unroll
                    for (int e = 0; e < 4; ++e)
#pragma unroll
                        for (int jj = 0; jj < 4; ++jj)
                            acc[ii][jj] += qe[e] * kv[e][jj];
                }
            }
            const float abs_s = ab[s];
            const float* mbase = smask + (size_t)(s*BB + b) * LL * LL;
#pragma unroll
            for (int ii = 0; ii < 8; ++ii) {
                const float* mr = mbase + (size_t)(i0 + row0 + ii) * LL + j0 + lane;
#pragma unroll
                for (int jj = 0; jj < 4; ++jj)
                    sreg[ii][jj] += __ldg(mr + 32*jj) * (acc[ii][jj] + abs_s);
            }
        }

        // ---- online softmax update ----
        float amv[4];
#pragma unroll
        for (int jj = 0; jj < 4; ++jj)
            amv[jj] = __ldg(amask + (size_t)b * LL + j0 + lane + 32*jj);

#pragma unroll
        for (int ii = 0; ii < 8; ++ii) {
            float lg[4];
            float mt = -1e30f;
#pragma unroll
            for (int jj = 0; jj < 4; ++jj) {
                lg[jj] = sreg[ii][jj] * 0.125f + amv[jj];
                mt = fmaxf(mt, lg[jj]);
            }
            mt = warp_max(mt);
            float mnew = fmaxf(mrow[ii], mt);
            float corr = __expf(mrow[ii] - mnew);
            mrow[ii] = mnew;
            float psum = 0.f;
#pragma unroll
            for (int jj = 0; jj < 4; ++jj) {
                float p = __expf(lg[jj] - mnew);
                probs[(row0 + ii) * 132 + lane + 32*jj] = p;
                psum += p;
            }
            psum = warp_sum(psum);
            lrow[ii] = lrow[ii] * corr + psum;
            ctx[ii][0] *= corr;
            ctx[ii][1] *= corr;
        }
        __syncwarp();

        // ---- PV: ctx += probs(rows) @ V(tile) ----
#pragma unroll 4
        for (int j4 = 0; j4 < 32; ++j4) {
            float v0[4], v1[4];
#pragma unroll
            for (int x = 0; x < 4; ++x) {
                const float* vr = &vt[(j4*4 + x) * 66];
                v0[x] = vr[lane];
                v1[x] = vr[lane + 32];
            }
#pragma unroll
            for (int ii = 0; ii < 8; ++ii) {
                float4 p4 = *(const float4*)&probs[(row0 + ii) * 132 + j4*4];
                ctx[ii][0] += p4.x*v0[0] + p4.y*v0[1] + p4.z*v0[2] + p4.w*v0[3];
                ctx[ii][1] += p4.x*v1[0] + p4.y*v1[1] + p4.z*v1[2] + p4.w*v1[3];
            }
        }
    }

    // ---- finalize ----
#pragma unroll
    for (int ii = 0; ii < 8; ++ii) {
        const int ig = i0 + row0 + ii;
        float inv = 1.f / lrow[ii];
        float* op = out + (size_t)(b * LL + ig) * (HH*DD) + h * DD;
        op[lane]      = ctx[ii][0] * inv;
        op[lane + 32] = ctx[ii][1] * inv;
    }
}

// =============================================================================
extern "C" void kernel_launch(void* const* d_in, const int* in_sizes, int n_in,
                              void* d_out, int out_size)
{
    const float* hs   = (const float*)d_in[0];
    const float* am   = (const float*)d_in[1];
    const float* smk  = (const float*)d_in[2];
    const float* Wq   = (const float*)d_in[3];
    const float* bq   = (const float*)d_in[4];
    const float* Wk   = (const float*)d_in[5];
    const float* bk   = (const float*)d_in[6];
    const float* Wv   = (const float*)d_in[7];
    const float* bv   = (const float*)d_in[8];
    const float* bili = (const float*)d_in[9];
    const float* absb = (const float*)d_in[10];
    float* out = (float*)d_out;

    qkv_kernel<<<dim3(64, 12, 3), 256>>>(hs, Wq, bq, Wk, bk, Wv, bv);
    qb_kernel<<<dim3(128, 12, 5), 256>>>(bili);

    const int smem_bytes = ATTN_SMEM_FLOATS * (int)sizeof(float);
    cudaFuncSetAttribute(attn_kernel, cudaFuncAttributeMaxDynamicSharedMemorySize, smem_bytes);
    attn_kernel<<<dim3(8, 192), 256, smem_bytes>>>(smk, am, absb, out);
}

// round 3
// speedup vs baseline: 1.4775x; 1.0366x over previous
#include <cuda_runtime.h>
#include <math.h>

#define BB 16
#define LL 512
#define HIDN 768
#define HH 12
#define DD 64
#define NSTRUCT 5
#define BH (BB*HH)   // 192

typedef unsigned long long ull;

// ---- packed f32x2 helpers (FFMA2/FMUL2 — ptxas never auto-generates these) ----
__device__ __forceinline__ void fma2(ull &d, ull a, ull b) {
    asm("fma.rn.f32x2 %0, %1, %2, %0;" : "+l"(d) : "l"(a), "l"(b));
}
__device__ __forceinline__ void mul2(ull &d, ull s) {
    asm("mul.rn.f32x2 %0, %0, %1;" : "+l"(d) : "l"(s));
}
__device__ __forceinline__ ull pack2(float lo, float hi) {
    ull r; asm("mov.b64 %0, {%1, %2};" : "=l"(r) : "f"(lo), "f"(hi)); return r;
}
__device__ __forceinline__ float2 unpack2(ull v) {
    float2 r; asm("mov.b64 {%0, %1}, %2;" : "=f"(r.x), "=f"(r.y) : "l"(v)); return r;
}

// ---------------- scratch ----------------
__device__ float g_Q [BH * LL * DD];
__device__ float g_K [BH * LL * DD];
__device__ float g_V [BH * LL * DD];
__device__ float g_QB[NSTRUCT * BH * LL * DD];

// =============================================================================
// Kernel 1: fused QKV projection. 128x64 tile, BK=16, 256 thr, 8x4 micro,
// k-parity-packed FFMA2, As [m][k] / Bs [n][k] pad 18.
// =============================================================================
__global__ void __launch_bounds__(256) qkv_kernel(
    const float* __restrict__ hs,
    const float* __restrict__ Wq, const float* __restrict__ bq,
    const float* __restrict__ Wk, const float* __restrict__ bk,
    const float* __restrict__ Wv, const float* __restrict__ bv)
{
    const int z = blockIdx.z;
    const float* W    = (z == 0) ? Wq : (z == 1) ? Wk : Wv;
    const float* bias = (z == 0) ? bq : (z == 1) ? bk : bv;
    float* dst        = (z == 0) ? g_Q : (z == 1) ? g_K : g_V;

    __shared__ __align__(16) float As[128 * 18];  // [m][k] pad 18
    __shared__ __align__(16) float Bs[64 * 18];   // [n][k] pad 18

    const int t  = threadIdx.x;
    const int m0 = blockIdx.x * 128;
    const int n0 = blockIdx.y * 64;
    const int r  = t >> 2;        // 0..63
    const int kq = t & 3;         // k quad
    const int ty = t >> 4;        // 0..15 -> 8 rows each
    const int tx = t & 15;        // 0..15 -> cols tx + 16*j

    ull ck[8][4];
#pragma unroll
    for (int i = 0; i < 8; i++)
#pragma unroll
        for (int j = 0; j < 4; j++) ck[i][j] = 0ULL;

    float4 pa0 = *(const float4*)(hs + (size_t)(m0 + r)      * HIDN + kq * 4);
    float4 pa1 = *(const float4*)(hs + (size_t)(m0 + 64 + r) * HIDN + kq * 4);
    float4 pb  = *(const float4*)(W  + (size_t)(n0 + r)      * HIDN + kq * 4);

    for (int k0 = 0; k0 < HIDN; k0 += 16) {
        {
            float* a0 = &As[r * 18 + kq * 4];
            a0[0] = pa0.x; a0[1] = pa0.y; a0[2] = pa0.z; a0[3] = pa0.w;
            float* a1 = &As[(r + 64) * 18 + kq * 4];
            a1[0] = pa1.x; a1[1] = pa1.y; a1[2] = pa1.z; a1[3] = pa1.w;
            float* b0 = &Bs[r * 18 + kq * 4];
            b0[0] = pb.x; b0[1] = pb.y; b0[2] = pb.z; b0[3] = pb.w;
        }
        __syncthreads();

        if (k0 + 16 < HIDN) {
            pa0 = *(const float4*)(hs + (size_t)(m0 + r)      * HIDN + k0 + 16 + kq * 4);
            pa1 = *(const float4*)(hs + (size_t)(m0 + 64 + r) * HIDN + k0 + 16 + kq * 4);
            pb  = *(const float4*)(W  + (size_t)(n0 + r)      * HIDN + k0 + 16 + kq * 4);
        }

#pragma unroll
        for (int k2 = 0; k2 < 8; ++k2) {
            ull b2[4];
#pragma unroll
            for (int j = 0; j < 4; ++j)
                b2[j] = *(const ull*)&Bs[(tx + 16*j) * 18 + 2*k2];
#pragma unroll
            for (int i = 0; i < 8; ++i) {
                ull a2 = *(const ull*)&As[(ty*8 + i) * 18 + 2*k2];
#pragma unroll
                for (int j = 0; j < 4; ++j) fma2(ck[i][j], a2, b2[j]);
            }
        }
        __syncthreads();
    }

    const int h = n0 >> 6;
    float bj[4];
#pragma unroll
    for (int j = 0; j < 4; ++j) bj[j] = bias[n0 + tx + 16*j];
#pragma unroll
    for (int i = 0; i < 8; i++) {
        int m = m0 + ty*8 + i;
        int b = m >> 9, l = m & 511;
        float* dp = dst + ((size_t)(b*HH + h) * LL + l) * DD;
#pragma unroll
        for (int j = 0; j < 4; ++j) {
            float2 v = unpack2(ck[i][j]);
            dp[tx + 16*j] = v.x + v.y + bj[j];
        }
    }
}

// =============================================================================
// Kernel 2: QB[s,b,h,l,:] = Q[b,h,l,:] @ bili[s,h]  (unchanged; ~4% of runtime)
// =============================================================================
__global__ void __launch_bounds__(256) qb_kernel(const float* __restrict__ bili)
{
    const int mt = blockIdx.x, h = blockIdx.y, s = blockIdx.z;
    const int m0 = mt * 64;
    const int b = m0 >> 9, l0 = m0 & 511;
    const float* qbase = g_Q + (size_t)(b*HH + h) * LL * DD;
    const float* Bm    = bili + (size_t)(s*HH + h) * DD * DD;
    float* dst         = g_QB + (size_t)((s*BB + b)*HH + h) * LL * DD;

    __shared__ __align__(16) float As[16 * 68];
    __shared__ __align__(16) float Bs[16 * 68];

    const int t = threadIdx.x;
    const int mload = t >> 2, kv = t & 3;
    const int kl = t >> 4, nv = t & 15;
    const int ty = t >> 4, tx = t & 15;

    float c[4][4];
#pragma unroll
    for (int i = 0; i < 4; i++)
#pragma unroll
        for (int j = 0; j < 4; j++) c[i][j] = 0.f;

    for (int k0 = 0; k0 < DD; k0 += 16) {
        float4 a4 = *(const float4*)(qbase + (size_t)(l0 + mload) * DD + k0 + kv * 4);
        As[(kv*4+0)*68 + mload] = a4.x;
        As[(kv*4+1)*68 + mload] = a4.y;
        As[(kv*4+2)*68 + mload] = a4.z;
        As[(kv*4+3)*68 + mload] = a4.w;
        float4 b4 = *(const float4*)(Bm + (size_t)(k0 + kl) * DD + nv * 4);
        Bs[kl*68 + nv*4+0] = b4.x;
        Bs[kl*68 + nv*4+1] = b4.y;
        Bs[kl*68 + nv*4+2] = b4.z;
        Bs[kl*68 + nv*4+3] = b4.w;
        __syncthreads();
#pragma unroll
        for (int k = 0; k < 16; k++) {
            float4 av4 = *(const float4*)&As[k*68 + ty*4];
            float4 bv4 = *(const float4*)&Bs[k*68 + tx*4];
            float a[4] = {av4.x, av4.y, av4.z, av4.w};
            float bb[4] = {bv4.x, bv4.y, bv4.z, bv4.w};
#pragma unroll
            for (int i = 0; i < 4; i++)
#pragma unroll
                for (int j = 0; j < 4; j++) c[i][j] += a[i] * bb[j];
        }
        __syncthreads();
    }

#pragma unroll
    for (int i = 0; i < 4; i++)
#pragma unroll
        for (int j = 0; j < 4; j++)
            dst[(size_t)(l0 + ty*4 + i) * DD + tx*4 + j] = c[i][j];
}

// =============================================================================
// Kernel 3: fused attention, flash-style, FFMA2-packed over reduction parity.
//  kt: [j][d] pad 66 (K tile, natural copy)   vt: [d][j] pad 130 (V transposed)
//  smem: qall[6][64][64] | kt 128*66 | vt 64*130 | probs 64*132
// =============================================================================
#define ATTN_SMEM_FLOATS (6*64*64 + 128*66 + 64*130 + 64*132)

__device__ __forceinline__ float warp_max(float v) {
#pragma unroll
    for (int off = 16; off > 0; off >>= 1)
        v = fmaxf(v, __shfl_xor_sync(0xffffffffu, v, off));
    return v;
}
__device__ __forceinline__ float warp_sum(float v) {
#pragma unroll
    for (int off = 16; off > 0; off >>= 1)
        v += __shfl_xor_sync(0xffffffffu, v, off);
    return v;
}

__global__ void __launch_bounds__(256) attn_kernel(
    const float* __restrict__ smask,   // [S,B,1,L,L]
    const float* __restrict__ amask,   // [B,1,1,L]
    const float* __restrict__ absb,    // [S,H]
    float* __restrict__ out)           // [B,L,H*D]
{
    extern __shared__ float sh[];
    float* qall  = sh;                      // 24576
    float* kt    = sh + 6*64*64;            // [j][d] pad 66 : 8448
    float* vt    = kt + 128*66;             // [d][j] pad 130: 8320
    float* probs = vt + 64*130;             // [row][j] pad 132: 8448

    const int t    = threadIdx.x;
    const int w    = t >> 5;
    const int lane = t & 31;
    const int bh   = blockIdx.y;
    const int b = bh / HH, h = bh % HH;
    const int i0 = blockIdx.x * 64;

    const float* Qb = g_Q + (size_t)bh * LL * DD;
    const float* Kb = g_K + (size_t)bh * LL * DD;
    const float* Vb = g_V + (size_t)bh * LL * DD;

    // ---- load q + 5 qb row-blocks into qall ----
    for (int f = t; f < 6 * 64 * 16; f += 256) {
        int c = f >> 10;
        int r = (f >> 4) & 63;
        int dv = f & 15;
        const float* src = (c == 0)
            ? (Qb + (size_t)(i0 + r) * DD + dv * 4)
            : (g_QB + (size_t)((c - 1) * BB + b) * HH * LL * DD
                    + (size_t)h * LL * DD + (size_t)(i0 + r) * DD + dv * 4);
        float4 v4 = *(const float4*)src;
        float* dp = qall + (c * 64 + r) * 64 + dv * 4;
        dp[0] = v4.x; dp[1] = v4.y; dp[2] = v4.z; dp[3] = v4.w;
    }

    float ab[NSTRUCT];
#pragma unroll
    for (int s = 0; s < NSTRUCT; ++s) ab[s] = __ldg(absb + s*HH + h);

    float mrow[8], lrow[8];
    ull ctx2[8][2];
#pragma unroll
    for (int i = 0; i < 8; ++i) {
        mrow[i] = -1e30f; lrow[i] = 0.f;
        ctx2[i][0] = 0ULL; ctx2[i][1] = 0ULL;
    }

    const int row0 = w * 8;

    for (int jt = 0; jt < 4; ++jt) {
        const int j0 = jt * 128;
        __syncthreads();   // previous-tile readers done
        // K tile: natural [j][d]; V tile: transposed [d][j]
        for (int f = t; f < 2048; f += 256) {
            int j = f >> 4, dv = f & 15;
            float4 k4 = *(const float4*)(Kb + (size_t)(j0 + j) * DD + dv * 4);
            float* kp = &kt[j * 66 + dv * 4];
            *(float2*)(kp)     = make_float2(k4.x, k4.y);
            *(float2*)(kp + 2) = make_float2(k4.z, k4.w);
            float4 v4 = *(const float4*)(Vb + (size_t)(j0 + j) * DD + dv * 4);
            vt[(dv*4+0)*130 + j] = v4.x;
            vt[(dv*4+1)*130 + j] = v4.y;
            vt[(dv*4+2)*130 + j] = v4.z;
            vt[(dv*4+3)*130 + j] = v4.w;
        }
        __syncthreads();

        float sreg[8][4];

        for (int c = 0; c < 6; ++c) {
            ull acc2[8][4];
#pragma unroll
            for (int i = 0; i < 8; ++i)
#pragma unroll
                for (int j = 0; j < 4; ++j) acc2[i][j] = 0ULL;

            const float* qc = qall + (c * 64 + row0) * 64;
#pragma unroll 4
            for (int d4 = 0; d4 < 16; ++d4) {
                ull kkA[4], kkB[4];
#pragma unroll
                for (int jj = 0; jj < 4; ++jj) {
                    const float* kp = &kt[(lane + 32*jj) * 66 + d4 * 4];
                    kkA[jj] = *(const ull*)(kp);
                    kkB[jj] = *(const ull*)(kp + 2);
                }
#pragma unroll
                for (int ii = 0; ii < 8; ++ii) {
                    float4 q4 = *(const float4*)(qc + ii * 64 + d4 * 4);
                    ull q01 = pack2(q4.x, q4.y);
                    ull q23 = pack2(q4.z, q4.w);
#pragma unroll
                    for (int jj = 0; jj < 4; ++jj) {
                        fma2(acc2[ii][jj], q01, kkA[jj]);
                        fma2(acc2[ii][jj], q23, kkB[jj]);
                    }
                }
            }

            if (c == 0) {
#pragma unroll
                for (int ii = 0; ii < 8; ++ii)
#pragma unroll
                    for (int jj = 0; jj < 4; ++jj) {
                        float2 v = unpack2(acc2[ii][jj]);
                        sreg[ii][jj] = v.x + v.y;
                    }
            } else {
                const float abs_s = ab[c - 1];
                const float* mbase = smask + (size_t)((c-1)*BB + b) * LL * LL;
#pragma unroll
                for (int ii = 0; ii < 8; ++ii) {
                    const float* mr = mbase + (size_t)(i0 + row0 + ii) * LL + j0 + lane;
#pragma unroll
                    for (int jj = 0; jj < 4; ++jj) {
                        float2 v = unpack2(acc2[ii][jj]);
                        sreg[ii][jj] += __ldg(mr + 32*jj) * (v.x + v.y + abs_s);
                    }
                }
            }
        }

        // ---- online softmax update ----
        float amv[4];
#pragma unroll
        for (int jj = 0; jj < 4; ++jj)
            amv[jj] = __ldg(amask + (size_t)b * LL + j0 + lane + 32*jj);

#pragma unroll
        for (int ii = 0; ii < 8; ++ii) {
            float lg[4];
            float mt = -1e30f;
#pragma unroll
            for (int jj = 0; jj < 4; ++jj) {
                lg[jj] = sreg[ii][jj] * 0.125f + amv[jj];
                mt = fmaxf(mt, lg[jj]);
            }
            mt = warp_max(mt);
            float mnew = fmaxf(mrow[ii], mt);
            float corr = __expf(mrow[ii] - mnew);
            mrow[ii] = mnew;
            float psum = 0.f;
#pragma unroll
            for (int jj = 0; jj < 4; ++jj) {
                float p = __expf(lg[jj] - mnew);
                probs[(row0 + ii) * 132 + lane + 32*jj] = p;
                psum += p;
            }
            psum = warp_sum(psum);
            lrow[ii] = lrow[ii] * corr + psum;
            ull c2 = pack2(corr, corr);
            mul2(ctx2[ii][0], c2);
            mul2(ctx2[ii][1], c2);
        }
        __syncwarp();

        // ---- PV: packed over j-parity; vt [d][j], probs adjacent-j pairs ----
        const float* vr0 = &vt[lane * 130];
        const float* vr1 = &vt[(lane + 32) * 130];
#pragma unroll 2
        for (int j2 = 0; j2 < 64; ++j2) {
            ull vv0 = *(const ull*)(vr0 + 2*j2);
            ull vv1 = *(const ull*)(vr1 + 2*j2);
#pragma unroll
            for (int ii = 0; ii < 8; ++ii) {
                ull pp = *(const ull*)&probs[(row0 + ii) * 132 + 2*j2];
                fma2(ctx2[ii][0], pp, vv0);
                fma2(ctx2[ii][1], pp, vv1);
            }
        }
    }

    // ---- finalize ----
#pragma unroll
    for (int ii = 0; ii < 8; ++ii) {
        const int ig = i0 + row0 + ii;
        float inv = 1.f / lrow[ii];
        float* op = out + (size_t)(b * LL + ig) * (HH*DD) + h * DD;
        float2 c0 = unpack2(ctx2[ii][0]);
        float2 c1 = unpack2(ctx2[ii][1]);
        op[lane]      = (c0.x + c0.y) * inv;
        op[lane + 32] = (c1.x + c1.y) * inv;
    }
}

// =============================================================================
extern "C" void kernel_launch(void* const* d_in, const int* in_sizes, int n_in,
                              void* d_out, int out_size)
{
    const float* hs   = (const float*)d_in[0];
    const float* am   = (const float*)d_in[1];
    const float* smk  = (const float*)d_in[2];
    const float* Wq   = (const float*)d_in[3];
    const float* bq   = (const float*)d_in[4];
    const float* Wk   = (const float*)d_in[5];
    const float* bk   = (const float*)d_in[6];
    const float* Wv   = (const float*)d_in[7];
    const float* bv   = (const float*)d_in[8];
    const float* bili = (const float*)d_in[9];
    const float* absb = (const float*)d_in[10];
    float* out = (float*)d_out;

    qkv_kernel<<<dim3(64, 12, 3), 256>>>(hs, Wq, bq, Wk, bk, Wv, bv);
    qb_kernel<<<dim3(128, 12, 5), 256>>>(bili);

    const int smem_bytes = ATTN_SMEM_FLOATS * (int)sizeof(float);
    cudaFuncSetAttribute(attn_kernel, cudaFuncAttributeMaxDynamicSharedMemorySize, smem_bytes);
    attn_kernel<<<dim3(8, 192), 256, smem_bytes>>>(smk, am, absb, out);
}

// round 4
// speedup vs baseline: 1.5875x; 1.0745x over previous
#include <cuda_runtime.h>
#include <math.h>

#define BB 16
#define LL 512
#define HIDN 768
#define HH 12
#define DD 64
#define NSTRUCT 5
#define BH (BB*HH)   // 192

typedef unsigned long long ull;

// ---- packed f32x2 helpers ----
__device__ __forceinline__ void fma2(ull &d, ull a, ull b) {
    asm("fma.rn.f32x2 %0, %1, %2, %0;" : "+l"(d) : "l"(a), "l"(b));
}
__device__ __forceinline__ void mul2(ull &d, ull s) {
    asm("mul.rn.f32x2 %0, %0, %1;" : "+l"(d) : "l"(s));
}
__device__ __forceinline__ ull pack2(float lo, float hi) {
    ull r; asm("mov.b64 %0, {%1, %2};" : "=l"(r) : "f"(lo), "f"(hi)); return r;
}
__device__ __forceinline__ float2 unpack2(ull v) {
    float2 r; asm("mov.b64 {%0, %1}, %2;" : "=f"(r.x), "=f"(r.y) : "l"(v)); return r;
}

// ---------------- scratch ----------------
__device__ float    g_Q [BH * LL * DD];
__device__ float    g_K [BH * LL * DD];
__device__ float    g_V [BH * LL * DD];
__device__ float    g_QB[NSTRUCT * BH * LL * DD];
__device__ unsigned g_MB[NSTRUCT * BB * LL * (LL/32)];   // packed structure mask

// =============================================================================
// Kernel 0: pack structure mask to bits. One warp -> one 32-bit word (ballot).
// =============================================================================
__global__ void __launch_bounds__(256) pack_mask(const float* __restrict__ smask)
{
    size_t e = (size_t)blockIdx.x * 256 + threadIdx.x;
    float v = smask[e];
    unsigned bal = __ballot_sync(0xffffffffu, v != 0.f);
    if ((threadIdx.x & 31) == 0) g_MB[e >> 5] = bal;
}

// =============================================================================
// Kernel 1: fused QKV projection. 128x128 tile, BK=16, 256 thr, 8x8 micro,
// scalar FFMA (register-lean), As/Bs [k][*] pad 132, register prefetch.
// =============================================================================
__global__ void __launch_bounds__(256, 2) qkv_kernel(
    const float* __restrict__ hs,
    const float* __restrict__ Wq, const float* __restrict__ bq,
    const float* __restrict__ Wk, const float* __restrict__ bk,
    const float* __restrict__ Wv, const float* __restrict__ bv)
{
    const int z = blockIdx.z;
    const float* W    = (z == 0) ? Wq : (z == 1) ? Wk : Wv;
    const float* bias = (z == 0) ? bq : (z == 1) ? bk : bv;
    float* dst        = (z == 0) ? g_Q : (z == 1) ? g_K : g_V;

    __shared__ __align__(16) float As[16 * 132];  // [k][m]
    __shared__ __align__(16) float Bs[16 * 132];  // [k][n]

    const int t  = threadIdx.x;
    const int m0 = blockIdx.x * 128;
    const int n0 = blockIdx.y * 128;
    const int r  = t >> 2;        // 0..63
    const int kq = t & 3;
    const int ty = t >> 4;        // 0..15 -> rows ty*8..+8
    const int tx = t & 15;        // cols tx*4..+4 and 64+tx*4..+4

    float c[8][8];
#pragma unroll
    for (int i = 0; i < 8; i++)
#pragma unroll
        for (int j = 0; j < 8; j++) c[i][j] = 0.f;

    float4 pa0 = *(const float4*)(hs + (size_t)(m0 + r)      * HIDN + kq * 4);
    float4 pa1 = *(const float4*)(hs + (size_t)(m0 + 64 + r) * HIDN + kq * 4);
    float4 pb0 = *(const float4*)(W  + (size_t)(n0 + r)      * HIDN + kq * 4);
    float4 pb1 = *(const float4*)(W  + (size_t)(n0 + 64 + r) * HIDN + kq * 4);

    for (int k0 = 0; k0 < HIDN; k0 += 16) {
        As[(kq*4+0)*132 + r]      = pa0.x;
        As[(kq*4+1)*132 + r]      = pa0.y;
        As[(kq*4+2)*132 + r]      = pa0.z;
        As[(kq*4+3)*132 + r]      = pa0.w;
        As[(kq*4+0)*132 + 64 + r] = pa1.x;
        As[(kq*4+1)*132 + 64 + r] = pa1.y;
        As[(kq*4+2)*132 + 64 + r] = pa1.z;
        As[(kq*4+3)*132 + 64 + r] = pa1.w;
        Bs[(kq*4+0)*132 + r]      = pb0.x;
        Bs[(kq*4+1)*132 + r]      = pb0.y;
        Bs[(kq*4+2)*132 + r]      = pb0.z;
        Bs[(kq*4+3)*132 + r]      = pb0.w;
        Bs[(kq*4+0)*132 + 64 + r] = pb1.x;
        Bs[(kq*4+1)*132 + 64 + r] = pb1.y;
        Bs[(kq*4+2)*132 + 64 + r] = pb1.z;
        Bs[(kq*4+3)*132 + 64 + r] = pb1.w;
        __syncthreads();

        if (k0 + 16 < HIDN) {
            pa0 = *(const float4*)(hs + (size_t)(m0 + r)      * HIDN + k0 + 16 + kq * 4);
            pa1 = *(const float4*)(hs + (size_t)(m0 + 64 + r) * HIDN + k0 + 16 + kq * 4);
            pb0 = *(const float4*)(W  + (size_t)(n0 + r)      * HIDN + k0 + 16 + kq * 4);
            pb1 = *(const float4*)(W  + (size_t)(n0 + 64 + r) * HIDN + k0 + 16 + kq * 4);
        }

#pragma unroll
        for (int k = 0; k < 16; k++) {
            float4 a0 = *(const float4*)&As[k*132 + ty*8];
            float4 a1 = *(const float4*)&As[k*132 + ty*8 + 4];
            float4 b0 = *(const float4*)&Bs[k*132 + tx*4];
            float4 b1 = *(const float4*)&Bs[k*132 + 64 + tx*4];
            float a[8] = {a0.x,a0.y,a0.z,a0.w,a1.x,a1.y,a1.z,a1.w};
            float bb[8] = {b0.x,b0.y,b0.z,b0.w,b1.x,b1.y,b1.z,b1.w};
#pragma unroll
            for (int i = 0; i < 8; i++)
#pragma unroll
                for (int j = 0; j < 8; j++) c[i][j] += a[i] * bb[j];
        }
        __syncthreads();
    }

    const int h0 = n0 >> 6;
    float bj[8];
#pragma unroll
    for (int j = 0; j < 4; ++j) bj[j]     = bias[n0 + tx*4 + j];
#pragma unroll
    for (int j = 0; j < 4; ++j) bj[4 + j] = bias[n0 + 64 + tx*4 + j];

#pragma unroll
    for (int i = 0; i < 8; i++) {
        int m = m0 + ty*8 + i;
        int b = m >> 9, l = m & 511;
        float4 o0, o1;
        o0.x = c[i][0]+bj[0]; o0.y = c[i][1]+bj[1]; o0.z = c[i][2]+bj[2]; o0.w = c[i][3]+bj[3];
        o1.x = c[i][4]+bj[4]; o1.y = c[i][5]+bj[5]; o1.z = c[i][6]+bj[6]; o1.w = c[i][7]+bj[7];
        *(float4*)(dst + ((size_t)(b*HH + h0)     * LL + l) * DD + tx*4) = o0;
        *(float4*)(dst + ((size_t)(b*HH + h0 + 1) * LL + l) * DD + tx*4) = o1;
    }
}

// =============================================================================
// Kernel 2: QB[s,b,h,l,:] = Q[b,h,l,:] @ bili[s,h]
// =============================================================================
__global__ void __launch_bounds__(256) qb_kernel(const float* __restrict__ bili)
{
    const int mt = blockIdx.x, h = blockIdx.y, s = blockIdx.z;
    const int m0 = mt * 64;
    const int b = m0 >> 9, l0 = m0 & 511;
    const float* qbase = g_Q + (size_t)(b*HH + h) * LL * DD;
    const float* Bm    = bili + (size_t)(s*HH + h) * DD * DD;
    float* dst         = g_QB + (size_t)((s*BB + b)*HH + h) * LL * DD;

    __shared__ __align__(16) float As[16 * 68];
    __shared__ __align__(16) float Bs[16 * 68];

    const int t = threadIdx.x;
    const int mload = t >> 2, kv = t & 3;
    const int kl = t >> 4, nv = t & 15;
    const int ty = t >> 4, tx = t & 15;

    float c[4][4];
#pragma unroll
    for (int i = 0; i < 4; i++)
#pragma unroll
        for (int j = 0; j < 4; j++) c[i][j] = 0.f;

    for (int k0 = 0; k0 < DD; k0 += 16) {
        float4 a4 = *(const float4*)(qbase + (size_t)(l0 + mload) * DD + k0 + kv * 4);
        As[(kv*4+0)*68 + mload] = a4.x;
        As[(kv*4+1)*68 + mload] = a4.y;
        As[(kv*4+2)*68 + mload] = a4.z;
        As[(kv*4+3)*68 + mload] = a4.w;
        float4 b4 = *(const float4*)(Bm + (size_t)(k0 + kl) * DD + nv * 4);
        Bs[kl*68 + nv*4+0] = b4.x;
        Bs[kl*68 + nv*4+1] = b4.y;
        Bs[kl*68 + nv*4+2] = b4.z;
        Bs[kl*68 + nv*4+3] = b4.w;
        __syncthreads();
#pragma unroll
        for (int k = 0; k < 16; k++) {
            float4 av4 = *(const float4*)&As[k*68 + ty*4];
            float4 bv4 = *(const float4*)&Bs[k*68 + tx*4];
            float a[4] = {av4.x, av4.y, av4.z, av4.w};
            float bb[4] = {bv4.x, bv4.y, bv4.z, bv4.w};
#pragma unroll
            for (int i = 0; i < 4; i++)
#pragma unroll
                for (int j = 0; j < 4; j++) c[i][j] += a[i] * bb[j];
        }
        __syncthreads();
    }

#pragma unroll
    for (int i = 0; i < 4; i++)
#pragma unroll
        for (int j = 0; j < 4; j++)
            dst[(size_t)(l0 + ty*4 + i) * DD + tx*4 + j] = c[i][j];
}

// =============================================================================
// Kernel 3: fused attention, flash-style, FFMA2, bitmask structure masks.
// =============================================================================
#define ATTN_SMEM_FLOATS (6*64*64 + 128*66 + 64*130 + 64*132)

__device__ __forceinline__ float warp_max(float v) {
#pragma unroll
    for (int off = 16; off > 0; off >>= 1)
        v = fmaxf(v, __shfl_xor_sync(0xffffffffu, v, off));
    return v;
}
__device__ __forceinline__ float warp_sum(float v) {
#pragma unroll
    for (int off = 16; off > 0; off >>= 1)
        v += __shfl_xor_sync(0xffffffffu, v, off);
    return v;
}

__global__ void __launch_bounds__(256) attn_kernel(
    const float* __restrict__ amask,   // [B,1,1,L]
    const float* __restrict__ absb,    // [S,H]
    float* __restrict__ out)           // [B,L,H*D]
{
    extern __shared__ float sh[];
    float* qall  = sh;                      // 24576
    float* kt    = sh + 6*64*64;            // [j][d] pad 66 : 8448
    float* vt    = kt + 128*66;             // [d][j] pad 130: 8320
    float* probs = vt + 64*130;             // [row][j] pad 132: 8448

    const int t    = threadIdx.x;
    const int w    = t >> 5;
    const int lane = t & 31;
    const int bh   = blockIdx.y;
    const int b = bh / HH, h = bh % HH;
    const int i0 = blockIdx.x * 64;

    const float* Qb = g_Q + (size_t)bh * LL * DD;
    const float* Kb = g_K + (size_t)bh * LL * DD;
    const float* Vb = g_V + (size_t)bh * LL * DD;

    for (int f = t; f < 6 * 64 * 16; f += 256) {
        int c = f >> 10;
        int r = (f >> 4) & 63;
        int dv = f & 15;
        const float* src = (c == 0)
            ? (Qb + (size_t)(i0 + r) * DD + dv * 4)
            : (g_QB + (size_t)((c - 1) * BB + b) * HH * LL * DD
                    + (size_t)h * LL * DD + (size_t)(i0 + r) * DD + dv * 4);
        float4 v4 = *(const float4*)src;
        float* dp = qall + (c * 64 + r) * 64 + dv * 4;
        dp[0] = v4.x; dp[1] = v4.y; dp[2] = v4.z; dp[3] = v4.w;
    }

    float ab[NSTRUCT];
#pragma unroll
    for (int s = 0; s < NSTRUCT; ++s) ab[s] = __ldg(absb + s*HH + h);

    float mrow[8], lrow[8];
    ull ctx2[8][2];
#pragma unroll
    for (int i = 0; i < 8; ++i) {
        mrow[i] = -1e30f; lrow[i] = 0.f;
        ctx2[i][0] = 0ULL; ctx2[i][1] = 0ULL;
    }

    const int row0 = w * 8;

    for (int jt = 0; jt < 4; ++jt) {
        const int j0 = jt * 128;
        __syncthreads();
        for (int f = t; f < 2048; f += 256) {
            int j = f >> 4, dv = f & 15;
            float4 k4 = *(const float4*)(Kb + (size_t)(j0 + j) * DD + dv * 4);
            float* kp = &kt[j * 66 + dv * 4];
            *(float2*)(kp)     = make_float2(k4.x, k4.y);
            *(float2*)(kp + 2) = make_float2(k4.z, k4.w);
            float4 v4 = *(const float4*)(Vb + (size_t)(j0 + j) * DD + dv * 4);
            vt[(dv*4+0)*130 + j] = v4.x;
            vt[(dv*4+1)*130 + j] = v4.y;
            vt[(dv*4+2)*130 + j] = v4.z;
            vt[(dv*4+3)*130 + j] = v4.w;
        }
        __syncthreads();

        float sreg[8][4];

        for (int c = 0; c < 6; ++c) {
            ull acc2[8][4];
#pragma unroll
            for (int i = 0; i < 8; ++i)
#pragma unroll
                for (int j = 0; j < 4; ++j) acc2[i][j] = 0ULL;

            const float* qc = qall + (c * 64 + row0) * 64;
#pragma unroll 4
            for (int d4 = 0; d4 < 16; ++d4) {
                ull kkA[4], kkB[4];
#pragma unroll
                for (int jj = 0; jj < 4; ++jj) {
                    const float* kp = &kt[(lane + 32*jj) * 66 + d4 * 4];
                    kkA[jj] = *(const ull*)(kp);
                    kkB[jj] = *(const ull*)(kp + 2);
                }
#pragma unroll
                for (int ii = 0; ii < 8; ++ii) {
                    const ull* qp = (const ull*)(qc + ii * 64 + d4 * 4);
                    ull q01 = qp[0];
                    ull q23 = qp[1];
#pragma unroll
                    for (int jj = 0; jj < 4; ++jj) {
                        fma2(acc2[ii][jj], q01, kkA[jj]);
                        fma2(acc2[ii][jj], q23, kkB[jj]);
                    }
                }
            }

            if (c == 0) {
#pragma unroll
                for (int ii = 0; ii < 8; ++ii)
#pragma unroll
                    for (int jj = 0; jj < 4; ++jj) {
                        float2 v = unpack2(acc2[ii][jj]);
                        sreg[ii][jj] = v.x + v.y;
                    }
            } else {
                const float abs_s = ab[c - 1];
                const int s = c - 1;
                // packed-bit mask: one uniform uint4 per row covers this 128-j tile
#pragma unroll
                for (int ii = 0; ii < 8; ++ii) {
                    const unsigned* mp = g_MB
                        + ((size_t)(s*BB + b) * LL + (i0 + row0 + ii)) * 16 + jt * 4;
                    uint4 mw = *(const uint4*)mp;
                    unsigned mj[4] = {mw.x, mw.y, mw.z, mw.w};
#pragma unroll
                    for (int jj = 0; jj < 4; ++jj) {
                        float sel = (float)((mj[jj] >> lane) & 1u);
                        float2 v = unpack2(acc2[ii][jj]);
                        sreg[ii][jj] += sel * (v.x + v.y + abs_s);
                    }
                }
            }
        }

        // ---- online softmax update ----
        float amv[4];
#pragma unroll
        for (int jj = 0; jj < 4; ++jj)
            amv[jj] = __ldg(amask + (size_t)b * LL + j0 + lane + 32*jj);

#pragma unroll
        for (int ii = 0; ii < 8; ++ii) {
            float lg[4];
            float mt = -1e30f;
#pragma unroll
            for (int jj = 0; jj < 4; ++jj) {
                lg[jj] = sreg[ii][jj] * 0.125f + amv[jj];
                mt = fmaxf(mt, lg[jj]);
            }
            mt = warp_max(mt);
            float mnew = fmaxf(mrow[ii], mt);
            float corr = __expf(mrow[ii] - mnew);
            mrow[ii] = mnew;
            float psum = 0.f;
#pragma unroll
            for (int jj = 0; jj < 4; ++jj) {
                float p = __expf(lg[jj] - mnew);
                probs[(row0 + ii) * 132 + lane + 32*jj] = p;
                psum += p;
            }
            psum = warp_sum(psum);
            lrow[ii] = lrow[ii] * corr + psum;
            ull c2 = pack2(corr, corr);
            mul2(ctx2[ii][0], c2);
            mul2(ctx2[ii][1], c2);
        }
        __syncwarp();

        // ---- PV ----
        const float* vr0 = &vt[lane * 130];
        const float* vr1 = &vt[(lane + 32) * 130];
#pragma unroll 2
        for (int j2 = 0; j2 < 64; ++j2) {
            ull vv0 = *(const ull*)(vr0 + 2*j2);
            ull vv1 = *(const ull*)(vr1 + 2*j2);
#pragma unroll
            for (int ii = 0; ii < 8; ++ii) {
                ull pp = *(const ull*)&probs[(row0 + ii) * 132 + 2*j2];
                fma2(ctx2[ii][0], pp, vv0);
                fma2(ctx2[ii][1], pp, vv1);
            }
        }
    }

    // ---- finalize ----
#pragma unroll
    for (int ii = 0; ii < 8; ++ii) {
        const int ig = i0 + row0 + ii;
        float inv = 1.f / lrow[ii];
        float* op = out + (size_t)(b * LL + ig) * (HH*DD) + h * DD;
        float2 c0 = unpack2(ctx2[ii][0]);
        float2 c1 = unpack2(ctx2[ii][1]);
        op[lane]      = (c0.x + c0.y) * inv;
        op[lane + 32] = (c1.x + c1.y) * inv;
    }
}

// =============================================================================
extern "C" void kernel_launch(void* const* d_in, const int* in_sizes, int n_in,
                              void* d_out, int out_size)
{
    const float* hs   = (const float*)d_in[0];
    const float* am   = (const float*)d_in[1];
    const float* smk  = (const float*)d_in[2];
    const float* Wq   = (const float*)d_in[3];
    const float* bq   = (const float*)d_in[4];
    const float* Wk   = (const float*)d_in[5];
    const float* bk   = (const float*)d_in[6];
    const float* Wv   = (const float*)d_in[7];
    const float* bv   = (const float*)d_in[8];
    const float* bili = (const float*)d_in[9];
    const float* absb = (const float*)d_in[10];
    float* out = (float*)d_out;

    pack_mask<<<(NSTRUCT*BB*LL*LL)/256, 256>>>(smk);
    qkv_kernel<<<dim3(64, 6, 3), 256>>>(hs, Wq, bq, Wk, bk, Wv, bv);
    qb_kernel<<<dim3(128, 12, 5), 256>>>(bili);

    const int smem_bytes = ATTN_SMEM_FLOATS * (int)sizeof(float);
    cudaFuncSetAttribute(attn_kernel, cudaFuncAttributeMaxDynamicSharedMemorySize, smem_bytes);
    attn_kernel<<<dim3(8, 192), 256, smem_bytes>>>(am, absb, out);
}